// round 4
// baseline (speedup 1.0000x reference)
#include <cuda_runtime.h>
#include <cuda_bf16.h>
#include <cstdint>

// Problem constants
#define NWAY   10
#define KSHOT  5
#define QQUERY 100
#define PRJ    16
#define DIMD   64
#define HW     49
#define NSUP   (NWAY * KSHOT * PRJ)      // 800
#define NQRY   (NWAY * QQUERY * PRJ)     // 16000
#define BTOT   (NSUP + NQRY)             // 16800
#define TRI    2080                      // 64*65/2
#define FEAT_STRIDE (DIMD * HW)          // 3136
#define XT_PITCH 68                      // padded row pitch for xT and gram
#define SUP_PER_CLASS (KSHOT * PRJ)      // 80

typedef unsigned long long ull;

// ---------- scratch (device globals; no allocation allowed) ----------
__device__ float g_suptv[NSUP * TRI];    // 800 x 2080 support tv vectors
__device__ float g_sup[NWAY * TRI];      // 10 x 2080 prototypes
__device__ float g_s2[NWAY];             // ||sup||^2
__device__ float g_part[128];            // loss partial sums

// ---------- packed f32x2 helpers ----------
__device__ __forceinline__ ull pack2(float lo, float hi) {
    ull r;
    asm("mov.b64 %0, {%1, %2};" : "=l"(r) : "f"(lo), "f"(hi));
    return r;
}
__device__ __forceinline__ void unpack2(ull v, float& lo, float& hi) {
    asm("mov.b64 {%0, %1}, %2;" : "=f"(lo), "=f"(hi) : "l"(v));
}
__device__ __forceinline__ void fma2(ull& d, ull a, ull b) {
    asm("fma.rn.f32x2 %0, %1, %2, %0;" : "+l"(d) : "l"(a), "l"(b));
}

// =====================================================================
// compute_tv: one image -> centered-dcov triu vector (TRI floats) in xT_tv.
// 256 threads. smem: xT_tv[49*68 (>=TRI)], gram[64*68], dgv[64], rmv[64], tmv[>=1]
// =====================================================================
__device__ __forceinline__ void compute_tv(
    const float* __restrict__ featb, float et,
    float* xT_tv, float* gram, float* dgv, float* rmv, float* tmv)
{
    const int tid = threadIdx.x;

    // 1) load transposed: xT[m][d] = feat[d][m]  (coalesced LDG, 4-way STS ok)
    for (int idx = tid; idx < DIMD * HW; idx += 256) {
        int d = idx / HW;
        int m = idx - d * HW;
        xT_tv[m * XT_PITCH + d] = featb[idx];
    }
    __syncthreads();

    // 2) gram: 16x16 thread grid, 4x4 tile each, packed f32x2 FMAs
    //    a-operand: half-warp broadcast; b-operand: LDS.128 conflict-free.
    {
        const int ty = tid >> 4, tx = tid & 15;
        const int i0 = ty << 2, j0 = tx << 2;
        ull acc[4][2] = {};
#pragma unroll 7
        for (int m = 0; m < HW; m++) {
            const float* rp = xT_tv + m * XT_PITCH;
            float4 av = *(const float4*)(rp + i0);
            ulonglong2 bv = *(const ulonglong2*)(rp + j0);
            ull a2;
            a2 = pack2(av.x, av.x); fma2(acc[0][0], a2, bv.x); fma2(acc[0][1], a2, bv.y);
            a2 = pack2(av.y, av.y); fma2(acc[1][0], a2, bv.x); fma2(acc[1][1], a2, bv.y);
            a2 = pack2(av.z, av.z); fma2(acc[2][0], a2, bv.x); fma2(acc[2][1], a2, bv.y);
            a2 = pack2(av.w, av.w); fma2(acc[3][0], a2, bv.x); fma2(acc[3][1], a2, bv.y);
        }
#pragma unroll
        for (int r = 0; r < 4; r++) {
            ulonglong2 st;
            st.x = acc[r][0];
            st.y = acc[r][1];
            *(ulonglong2*)(gram + (i0 + r) * XT_PITCH + j0) = st;
        }
    }
    __syncthreads();

    // 3) diagonal
    if (tid < DIMD) dgv[tid] = gram[tid * XT_PITCH + tid];
    __syncthreads();

    // 4) dcov + row sums (matrix symmetric -> row mean == col mean)
    {
        const int r = tid >> 2, qq = tid & 3;
        const float dgr = dgv[r];
        float* grow = gram + r * XT_PITCH + qq * 16;
        float ps = 0.0f;
#pragma unroll
        for (int cc = 0; cc < 16; cc++) {
            int c = qq * 16 + cc;
            float g = grow[cc];
            float dd = fmaxf(dgr + dgv[c] - 2.0f * g, 0.0f);
            float dc = sqrtf(fmaf(dd, et, 1e-5f));
            grow[cc] = dc;
            ps += dc;
        }
        // combine the 4 quarter-sums of this row (lanes 4a..4a+3 of one warp)
        ps += __shfl_xor_sync(0xffffffffu, ps, 1);
        ps += __shfl_xor_sync(0xffffffffu, ps, 2);
        if (qq == 0) rmv[r] = ps;   // row SUM (divide later)
    }
    __syncthreads();

    // 5) total sum (deterministic tree)
    if (tid < 32) {
        float s = rmv[tid] + rmv[tid + 32];
#pragma unroll
        for (int off = 16; off > 0; off >>= 1)
            s += __shfl_xor_sync(0xffffffffu, s, off);
        if (tid == 0) tmv[0] = s;
    }
    __syncthreads();

    // 6) triu extraction with centering: v = dcov - rm_i - rm_j + tm
    {
        const float tmval = tmv[0] * (1.0f / 4096.0f);
        for (int k = tid; k < TRI; k += 256) {
            float disc = 16641.0f - 8.0f * (float)k;   // 129^2 - 8k
            int i = (int)((129.0f - sqrtf(disc)) * 0.5f);
            if (i > 63) i = 63;
            if (i < 0) i = 0;
            while (i * (129 - i) / 2 > k) --i;
            while ((i + 1) * (128 - i) / 2 <= k) ++i;
            int j = i + (k - i * (129 - i) / 2);
            xT_tv[k] = gram[i * XT_PITCH + j]
                       - (rmv[i] + rmv[j]) * (1.0f / 64.0f) + tmval;
        }
    }
    // caller must __syncthreads() before consuming xT_tv
}

// =====================================================================
// Kernel A: support tv vectors -> g_suptv
// =====================================================================
__global__ __launch_bounds__(256) void sup_tv_kernel(
    const float* __restrict__ feat, const float* __restrict__ temp)
{
    __shared__ __align__(16) float sXT[HW * XT_PITCH];
    __shared__ __align__(16) float sG[DIMD * XT_PITCH];
    __shared__ float sDG[DIMD], sRM[DIMD], sTM[4];

    const int b = blockIdx.x;
    const float et = expf(temp[0]);
    compute_tv(feat + (size_t)b * FEAT_STRIDE, et, sXT, sG, sDG, sRM, sTM);
    __syncthreads();
    float* dst = g_suptv + (size_t)b * TRI;
    for (int k = threadIdx.x; k < TRI; k += 256) dst[k] = sXT[k];
}

// =====================================================================
// Kernel B: prototypes (mean over 80) + ||sup||^2, grid = 10, deterministic
// =====================================================================
__global__ __launch_bounds__(256) void sup_reduce_kernel()
{
    __shared__ float sred[8];
    const int c = blockIdx.x;
    const int tid = threadIdx.x;
    float s2p = 0.0f;
    for (int k = tid; k < TRI; k += 256) {
        float s = 0.0f;
        const float* base = g_suptv + (size_t)(c * SUP_PER_CLASS) * TRI + k;
#pragma unroll
        for (int j = 0; j < SUP_PER_CLASS; j++) s += base[(size_t)j * TRI];
        float sv = s * (1.0f / (float)SUP_PER_CLASS);
        g_sup[c * TRI + k] = sv;
        s2p += sv * sv;
    }
    // deterministic block reduce
#pragma unroll
    for (int off = 16; off > 0; off >>= 1)
        s2p += __shfl_xor_sync(0xffffffffu, s2p, off);
    if ((tid & 31) == 0) sred[tid >> 5] = s2p;
    __syncthreads();
    if (tid == 0) {
        float t = 0.0f;
#pragma unroll
        for (int w = 0; w < 8; w++) t += sred[w];
        g_s2[c] = t;
    }
}

// =====================================================================
// Kernel C: fused query pass. 8 queries per CTA, supports staged in smem.
// Targets 2 CTAs/SM: 114,976 B dynamic smem each, 2x(114976+1024) <= 233472.
// dynamic smem layout (floats):
//   sup   [20800]
//   s2    [16]
//   xT/tv [3332]
//   gram  [4352]
//   dg    [64]  rm [64]  red [96]  tm [4]  col [12]
// =====================================================================
#define SM_SUP   0
#define SM_S2    20800
#define SM_XT    20816
#define SM_GRAM  24148
#define SM_DG    28500
#define SM_RM    28564
#define SM_RED   28628
#define SM_TM    28724
#define SM_COL   28728
#define SM_TOTALF 28744
#define QPC 8

static_assert(2 * (SM_TOTALF * 4 + 1024) <= 233472, "2 CTA/SM smem fit");

__global__ __launch_bounds__(256, 2) void query_kernel(
    const float* __restrict__ feat, const float* __restrict__ temp,
    float* __restrict__ out)
{
    extern __shared__ __align__(16) float smem[];
    float* sup_s = smem + SM_SUP;
    float* s2_s  = smem + SM_S2;
    float* sXT   = smem + SM_XT;
    float* sG    = smem + SM_GRAM;
    float* sDG   = smem + SM_DG;
    float* sRM   = smem + SM_RM;
    float* sRED  = smem + SM_RED;
    float* sTM   = smem + SM_TM;
    float* sCOL  = smem + SM_COL;

    const int tid = threadIdx.x;
    const float et = expf(temp[0]);

    // stage prototypes (vec4)
    for (int idx = tid; idx < (NWAY * TRI) / 4; idx += 256)
        ((float4*)sup_s)[idx] = ((const float4*)g_sup)[idx];
    if (tid < NWAY) s2_s[tid] = g_s2[tid];
    __syncthreads();

    for (int q = 0; q < QPC; q++) {
        const int qidx = blockIdx.x * QPC + q;            // 0..15999
        const float* featb = feat + (size_t)(NSUP + qidx) * FEAT_STRIDE;
        compute_tv(featb, et, sXT, sG, sDG, sRM, sTM);
        __syncthreads();

        // dot phase: q2 + 10 prototype dots, packed f32x2
        ull qa = 0;
        ull da[NWAY] = {};
        const ull* tvp = (const ull*)sXT;
        for (int kp = tid; kp < TRI / 2; kp += 256) {
            ull t2 = tvp[kp];
            fma2(qa, t2, t2);
#pragma unroll
            for (int c = 0; c < NWAY; c++) {
                ull sv = *((const ull*)(sup_s + c * TRI) + kp);
                fma2(da[c], t2, sv);
            }
        }
        float v[NWAY + 1];
        {
            float lo, hi;
            unpack2(qa, lo, hi); v[0] = lo + hi;
#pragma unroll
            for (int c = 0; c < NWAY; c++) { unpack2(da[c], lo, hi); v[c + 1] = lo + hi; }
        }
#pragma unroll
        for (int u = 0; u < NWAY + 1; u++) {
#pragma unroll
            for (int off = 16; off > 0; off >>= 1)
                v[u] += __shfl_xor_sync(0xffffffffu, v[u], off);
        }
        const int warp = tid >> 5, lane = tid & 31;
        if (lane == 0) {
#pragma unroll
            for (int u = 0; u < NWAY + 1; u++) sRED[warp * 12 + u] = v[u];
        }
        __syncthreads();
        if (tid < NWAY + 1) {
            float s = 0.0f;
#pragma unroll
            for (int w = 0; w < 8; w++) s += sRED[w * 12 + tid];
            sCOL[tid] = s;
        }
        __syncthreads();
        if (tid < NWAY) {
            float sc = -(sCOL[0] + s2_s[tid] - 2.0f * sCOL[tid + 1]);
            out[(size_t)qidx * NWAY + tid] = sc;
        }
        __syncthreads();   // protect sXT/sCOL before next query
    }
}

// =====================================================================
// Kernel D: log-softmax NLL loss, two deterministic stages
// =====================================================================
__global__ __launch_bounds__(128) void loss_part_kernel(
    const float* __restrict__ out, const long long* __restrict__ label)
{
    __shared__ float sred[4];
    const int qi = blockIdx.x * 128 + threadIdx.x;    // < 16000 (125*128)
    const float* srow = out + (size_t)qi * NWAY;
    float s[NWAY];
#pragma unroll
    for (int c = 0; c < NWAY; c++) s[c] = srow[c];
    float m = s[0];
#pragma unroll
    for (int c = 1; c < NWAY; c++) m = fmaxf(m, s[c]);
    float sum = 0.0f;
#pragma unroll
    for (int c = 0; c < NWAY; c++) sum += expf(s[c] - m);
    float lse = m + logf(sum);
    long long lab = label[qi];
    float val = lse - s[(int)lab];
#pragma unroll
    for (int off = 16; off > 0; off >>= 1)
        val += __shfl_xor_sync(0xffffffffu, val, off);
    if ((threadIdx.x & 31) == 0) sred[threadIdx.x >> 5] = val;
    __syncthreads();
    if (threadIdx.x == 0)
        g_part[blockIdx.x] = sred[0] + sred[1] + sred[2] + sred[3];
}

__global__ __launch_bounds__(128) void loss_final_kernel(float* __restrict__ out)
{
    __shared__ float sred[4];
    float v = (threadIdx.x < 125) ? g_part[threadIdx.x] : 0.0f;
#pragma unroll
    for (int off = 16; off > 0; off >>= 1)
        v += __shfl_xor_sync(0xffffffffu, v, off);
    if ((threadIdx.x & 31) == 0) sred[threadIdx.x >> 5] = v;
    __syncthreads();
    if (threadIdx.x == 0)
        out[(size_t)NQRY * NWAY] = (sred[0] + sred[1] + sred[2] + sred[3]) * (1.0f / (float)NQRY);
}

// =====================================================================
extern "C" void kernel_launch(void* const* d_in, const int* in_sizes, int n_in,
                              void* d_out, int out_size)
{
    const float* feat = (const float*)d_in[0];
    const float* temp = (const float*)d_in[1];
    const long long* label = (const long long*)d_in[2];
    float* out = (float*)d_out;

    cudaFuncSetAttribute(query_kernel,
                         cudaFuncAttributeMaxDynamicSharedMemorySize,
                         SM_TOTALF * 4);

    sup_tv_kernel<<<NSUP, 256>>>(feat, temp);
    sup_reduce_kernel<<<NWAY, 256>>>();
    query_kernel<<<NQRY / QPC, 256, SM_TOTALF * 4>>>(feat, temp, out);
    if (out_size >= NQRY * NWAY + 1) {
        loss_part_kernel<<<NQRY / 128, 128>>>(out, label);
        loss_final_kernel<<<1, 128>>>(out);
    }
}

// round 6
// speedup vs baseline: 1.2730x; 1.2730x over previous
#include <cuda_runtime.h>
#include <cuda_bf16.h>
#include <cstdint>

// Problem constants
#define NWAY   10
#define KSHOT  5
#define QQUERY 100
#define PRJ    16
#define DIMD   64
#define HW     49
#define NSUP   (NWAY * KSHOT * PRJ)      // 800
#define NQRY   (NWAY * QQUERY * PRJ)     // 16000
#define TRI    2080                      // 64*65/2
#define FEAT_STRIDE (DIMD * HW)          // 3136
#define XT_PITCH 68                      // padded row pitch for xT and gram
#define SUP_PER_CLASS (KSHOT * PRJ)      // 80
#define DCDIAG 0.0031622776601683794f    // sqrtf(1e-5f): dcov diagonal (dd==0 exact)

typedef unsigned long long ull;

// ---------- scratch (device globals; no allocation allowed) ----------
__device__ float g_suptv[NSUP * TRI];
__device__ float g_sup[NWAY * TRI];
__device__ float g_s2[NWAY];
__device__ float g_part[128];

// ---------- packed f32x2 helpers ----------
__device__ __forceinline__ ull pack2(float lo, float hi) {
    ull r;
    asm("mov.b64 %0, {%1, %2};" : "=l"(r) : "f"(lo), "f"(hi));
    return r;
}
__device__ __forceinline__ void unpack2(ull v, float& lo, float& hi) {
    asm("mov.b64 {%0, %1}, %2;" : "=f"(lo), "=f"(hi) : "l"(v));
}
__device__ __forceinline__ void fma2(ull& d, ull a, ull b) {
    asm("fma.rn.f32x2 %0, %1, %2, %0;" : "+l"(d) : "l"(a), "l"(b));
}

// triu index pack: (i*68+j) in low 16 bits, i in [16:24), j in [24:32)
__device__ __forceinline__ uint32_t pack_ij(int k) {
    float disc = 16641.0f - 8.0f * (float)k;       // 129^2 - 8k
    int i = (int)((129.0f - sqrtf(disc)) * 0.5f);
    if (i > 63) i = 63;
    if (i < 0) i = 0;
    while (i * (129 - i) / 2 > k) --i;
    while ((i + 1) * (128 - i) / 2 <= k) ++i;
    int j = i + (k - i * (129 - i) / 2);
    return (uint32_t)(i * XT_PITCH + j) | ((uint32_t)i << 16) | ((uint32_t)j << 24);
}

// =====================================================================
// bdc_body: xT (already populated, pitch 68) -> centered triu vector in
// xT_tv[0..TRI). Caller must have synced after filling xT.
// On exit tv is written but NOT synced (caller syncs before consuming).
// =====================================================================
__device__ __forceinline__ void bdc_body(
    float et, float* xT_tv, float* gram, float* rmv, const uint32_t* pk)
{
    const int tid = threadIdx.x;

    // 1) gram: 16x16 thread grid, 4x4 tile each, packed f32x2 FMAs
    {
        const int ty = tid >> 4, tx = tid & 15;
        const int i0 = ty << 2, j0 = tx << 2;
        ull acc[4][2] = {};
#pragma unroll 7
        for (int m = 0; m < HW; m++) {
            const float* rp = xT_tv + m * XT_PITCH;
            float4 av = *(const float4*)(rp + i0);
            ulonglong2 bv = *(const ulonglong2*)(rp + j0);
            ull a2;
            a2 = pack2(av.x, av.x); fma2(acc[0][0], a2, bv.x); fma2(acc[0][1], a2, bv.y);
            a2 = pack2(av.y, av.y); fma2(acc[1][0], a2, bv.x); fma2(acc[1][1], a2, bv.y);
            a2 = pack2(av.z, av.z); fma2(acc[2][0], a2, bv.x); fma2(acc[2][1], a2, bv.y);
            a2 = pack2(av.w, av.w); fma2(acc[3][0], a2, bv.x); fma2(acc[3][1], a2, bv.y);
        }
#pragma unroll
        for (int r = 0; r < 4; r++) {
            ulonglong2 st;
            st.x = acc[r][0];
            st.y = acc[r][1];
            *(ulonglong2*)(gram + (i0 + r) * XT_PITCH + j0) = st;
        }
    }
    __syncthreads();

    // 2) dcov + row sums, diag read inline (diag cells NEVER overwritten:
    //    dd==0 exactly on diagonal, dcov_diag = sqrt(1e-5) = DCDIAG)
    {
        const int r = tid >> 2, qq = tid & 3;
        const float dgr = gram[r * (XT_PITCH + 1)];
        float* grow = gram + r * XT_PITCH + qq * 16;
        float ps = 0.0f;
#pragma unroll
        for (int cc = 0; cc < 16; cc++) {
            int c = qq * 16 + cc;
            float dgc = gram[c * (XT_PITCH + 1)];
            float g = grow[cc];
            float dd = fmaxf(dgr + dgc - 2.0f * g, 0.0f);
            float dc = sqrtf(fmaf(dd, et, 1e-5f));
            if (c != r) grow[cc] = dc;       // keep original diag in place
            ps += dc;                         // dc == DCDIAG when c==r
        }
        ps += __shfl_xor_sync(0xffffffffu, ps, 1);
        ps += __shfl_xor_sync(0xffffffffu, ps, 2);
        if (qq == 0) rmv[r] = ps;            // row SUM
    }
    __syncthreads();

    // 3) per-warp redundant total (same xor-tree order as a single warp ->
    //    bit-identical across warps), then triu extraction with centering
    {
        const int lane = tid & 31;
        float s = rmv[lane] + rmv[lane + 32];
#pragma unroll
        for (int off = 16; off > 0; off >>= 1)
            s += __shfl_xor_sync(0xffffffffu, s, off);
        const float tmval = s * (1.0f / 4096.0f);

#pragma unroll
        for (int ss = 0; ss < 9; ss++) {
            int k = tid + 256 * ss;
            if (k < TRI) {
                uint32_t p = pk[ss];
                int goff = (int)(p & 0xFFFFu);
                int i = (int)((p >> 16) & 0xFFu);
                int j = (int)(p >> 24);
                float gval = (i == j) ? DCDIAG : gram[goff];
                xT_tv[k] = gval - (rmv[i] + rmv[j]) * (1.0f / 64.0f) + tmval;
            }
        }
    }
}

// =====================================================================
// Kernel A: support tv vectors -> g_suptv
// =====================================================================
__global__ __launch_bounds__(256) void sup_tv_kernel(
    const float* __restrict__ feat, const float* __restrict__ temp)
{
    __shared__ __align__(16) float sXT[HW * XT_PITCH];
    __shared__ __align__(16) float sG[DIMD * XT_PITCH];
    __shared__ float sRM[DIMD];

    const int tid = threadIdx.x;
    const int b = blockIdx.x;
    const float et = expf(temp[0]);

    uint32_t pk[9];
#pragma unroll
    for (int ss = 0; ss < 9; ss++) {
        int k = tid + 256 * ss;
        pk[ss] = (k < TRI) ? pack_ij(k) : 0u;
    }

    const float* featb = feat + (size_t)b * FEAT_STRIDE;
    for (int idx = tid; idx < DIMD * HW; idx += 256) {
        int d = idx / HW;
        int m = idx - d * HW;
        sXT[m * XT_PITCH + d] = featb[idx];
    }
    __syncthreads();

    bdc_body(et, sXT, sG, sRM, pk);
    __syncthreads();

    float* dst = g_suptv + (size_t)b * TRI;
    for (int k = tid; k < TRI; k += 256) dst[k] = sXT[k];
}

// =====================================================================
// Kernel B: prototypes (mean over 80) + ||sup||^2, grid = 10, deterministic
// =====================================================================
__global__ __launch_bounds__(256) void sup_reduce_kernel()
{
    __shared__ float sred[8];
    const int c = blockIdx.x;
    const int tid = threadIdx.x;
    float s2p = 0.0f;
    for (int k = tid; k < TRI; k += 256) {
        float s = 0.0f;
        const float* base = g_suptv + (size_t)(c * SUP_PER_CLASS) * TRI + k;
#pragma unroll
        for (int j = 0; j < SUP_PER_CLASS; j++) s += base[(size_t)j * TRI];
        float sv = s * (1.0f / (float)SUP_PER_CLASS);
        g_sup[c * TRI + k] = sv;
        s2p += sv * sv;
    }
#pragma unroll
    for (int off = 16; off > 0; off >>= 1)
        s2p += __shfl_xor_sync(0xffffffffu, s2p, off);
    if ((tid & 31) == 0) sred[tid >> 5] = s2p;
    __syncthreads();
    if (tid == 0) {
        float t = 0.0f;
#pragma unroll
        for (int w = 0; w < 8; w++) t += sred[w];
        g_s2[c] = t;
    }
}

// =====================================================================
// Kernel C: fused query pass. 8 queries per CTA, supports staged in smem,
// next query's feat prefetched into registers across the compute phases.
// 2 CTAs/SM: 2 x (114,976 + 1,024) = 232,000 <= 233,472 B.
// =====================================================================
#define SM_SUP   0
#define SM_S2    20800
#define SM_XT    20816
#define SM_GRAM  24148
#define SM_RM    28500
#define SM_RED   28564
#define SM_COL   28660
#define SM_TOTALF 28744
#define QPC 8

static_assert(2 * (SM_TOTALF * 4 + 1024) <= 233472, "2 CTA/SM smem fit");

__global__ __launch_bounds__(256, 2) void query_kernel(
    const float* __restrict__ feat, const float* __restrict__ temp,
    float* __restrict__ out)
{
    extern __shared__ __align__(16) float smem[];
    float* sup_s = smem + SM_SUP;
    float* s2_s  = smem + SM_S2;
    float* sXT   = smem + SM_XT;
    float* sG    = smem + SM_GRAM;
    float* sRM   = smem + SM_RM;
    float* sRED  = smem + SM_RED;
    float* sCOL  = smem + SM_COL;

    const int tid = threadIdx.x;
    const float et = expf(temp[0]);

    // ---- per-thread precomputation, reused across all 8 queries ----
    uint32_t pk[9];
#pragma unroll
    for (int ss = 0; ss < 9; ss++) {
        int k = tid + 256 * ss;
        pk[ss] = (k < TRI) ? pack_ij(k) : 0u;
    }
    const int cnt = (tid < 64) ? 13 : 12;     // 3136 = 12*256 + 64
    uint32_t sts_off[13];
#pragma unroll
    for (int j = 0; j < 13; j++) {
        int idx = tid + 256 * j;
        int d = idx / HW;
        int m = idx - d * HW;
        sts_off[j] = (uint32_t)(m * XT_PITCH + d);
    }

    // stage prototypes (vec4)
    for (int idx = tid; idx < (NWAY * TRI) / 4; idx += 256)
        ((float4*)sup_s)[idx] = ((const float4*)g_sup)[idx];
    if (tid < NWAY) s2_s[tid] = g_s2[tid];

    // prologue: prefetch query 0's feature map into registers
    float pf[13];
    {
        const float* fb = feat + (size_t)(NSUP + blockIdx.x * QPC) * FEAT_STRIDE;
#pragma unroll
        for (int j = 0; j < 13; j++)
            if (j < cnt) pf[j] = fb[tid + 256 * j];
    }
    __syncthreads();

    for (int q = 0; q < QPC; q++) {
        const int qidx = blockIdx.x * QPC + q;

        // transpose store from prefetched registers
#pragma unroll
        for (int j = 0; j < 13; j++)
            if (j < cnt) sXT[sts_off[j]] = pf[j];
        __syncthreads();

        // prefetch next query's features (latency hidden by gram/dcov/triu)
        if (q + 1 < QPC) {
            const float* fb = feat + (size_t)(NSUP + qidx + 1) * FEAT_STRIDE;
#pragma unroll
            for (int j = 0; j < 13; j++)
                if (j < cnt) pf[j] = fb[tid + 256 * j];
        }

        bdc_body(et, sXT, sG, sRM, pk);
        __syncthreads();

        // dot phase: q2 + 10 prototype dots, LDS.128 + packed f32x2
        ull qa = 0;
        ull da[NWAY] = {};
        const ulonglong2* tv4 = (const ulonglong2*)sXT;
        for (int k4 = tid; k4 < TRI / 4; k4 += 256) {
            ulonglong2 t = tv4[k4];
            fma2(qa, t.x, t.x);
            fma2(qa, t.y, t.y);
#pragma unroll
            for (int c = 0; c < NWAY; c++) {
                ulonglong2 sv = *((const ulonglong2*)(sup_s + c * TRI) + k4);
                fma2(da[c], t.x, sv.x);
                fma2(da[c], t.y, sv.y);
            }
        }
        float v[NWAY + 1];
        {
            float lo, hi;
            unpack2(qa, lo, hi); v[0] = lo + hi;
#pragma unroll
            for (int c = 0; c < NWAY; c++) { unpack2(da[c], lo, hi); v[c + 1] = lo + hi; }
        }
#pragma unroll
        for (int u = 0; u < NWAY + 1; u++) {
#pragma unroll
            for (int off = 16; off > 0; off >>= 1)
                v[u] += __shfl_xor_sync(0xffffffffu, v[u], off);
        }
        const int warp = tid >> 5, lane = tid & 31;
        if (lane == 0) {
#pragma unroll
            for (int u = 0; u < NWAY + 1; u++) sRED[warp * 12 + u] = v[u];
        }
        __syncthreads();
        if (tid < NWAY + 1) {
            float s = 0.0f;
#pragma unroll
            for (int w = 0; w < 8; w++) s += sRED[w * 12 + tid];
            sCOL[tid] = s;
        }
        __syncthreads();
        if (tid < NWAY) {
            float sc = -(sCOL[0] + s2_s[tid] - 2.0f * sCOL[tid + 1]);
            out[(size_t)qidx * NWAY + tid] = sc;
        }
        __syncthreads();   // protect sXT/sCOL before next query
    }
}

// =====================================================================
// Kernel D: log-softmax NLL loss, two deterministic stages
// =====================================================================
__global__ __launch_bounds__(128) void loss_part_kernel(
    const float* __restrict__ out, const long long* __restrict__ label)
{
    __shared__ float sred[4];
    const int qi = blockIdx.x * 128 + threadIdx.x;    // < 16000 (125*128)
    const float* srow = out + (size_t)qi * NWAY;
    float s[NWAY];
#pragma unroll
    for (int c = 0; c < NWAY; c++) s[c] = srow[c];
    float m = s[0];
#pragma unroll
    for (int c = 1; c < NWAY; c++) m = fmaxf(m, s[c]);
    float sum = 0.0f;
#pragma unroll
    for (int c = 0; c < NWAY; c++) sum += expf(s[c] - m);
    float lse = m + logf(sum);
    long long lab = label[qi];
    float val = lse - s[(int)lab];
#pragma unroll
    for (int off = 16; off > 0; off >>= 1)
        val += __shfl_xor_sync(0xffffffffu, val, off);
    if ((threadIdx.x & 31) == 0) sred[threadIdx.x >> 5] = val;
    __syncthreads();
    if (threadIdx.x == 0)
        g_part[blockIdx.x] = sred[0] + sred[1] + sred[2] + sred[3];
}

__global__ __launch_bounds__(128) void loss_final_kernel(float* __restrict__ out)
{
    __shared__ float sred[4];
    float v = (threadIdx.x < 125) ? g_part[threadIdx.x] : 0.0f;
#pragma unroll
    for (int off = 16; off > 0; off >>= 1)
        v += __shfl_xor_sync(0xffffffffu, v, off);
    if ((threadIdx.x & 31) == 0) sred[threadIdx.x >> 5] = v;
    __syncthreads();
    if (threadIdx.x == 0)
        out[(size_t)NQRY * NWAY] = (sred[0] + sred[1] + sred[2] + sred[3]) * (1.0f / (float)NQRY);
}

// =====================================================================
extern "C" void kernel_launch(void* const* d_in, const int* in_sizes, int n_in,
                              void* d_out, int out_size)
{
    const float* feat = (const float*)d_in[0];
    const float* temp = (const float*)d_in[1];
    const long long* label = (const long long*)d_in[2];
    float* out = (float*)d_out;

    cudaFuncSetAttribute(query_kernel,
                         cudaFuncAttributeMaxDynamicSharedMemorySize,
                         SM_TOTALF * 4);

    sup_tv_kernel<<<NSUP, 256>>>(feat, temp);
    sup_reduce_kernel<<<NWAY, 256>>>();
    query_kernel<<<NQRY / QPC, 256, SM_TOTALF * 4>>>(feat, temp, out);
    if (out_size >= NQRY * NWAY + 1) {
        loss_part_kernel<<<NQRY / 128, 128>>>(out, label);
        loss_final_kernel<<<1, 128>>>(out);
    }
}